// round 16
// baseline (speedup 1.0000x reference)
#include <cuda_runtime.h>
#include <cstdint>

#define NUM_NODES 100000
#define NUM_EDGES 50000
#define NUM_CONN  800000
#define IN_DIM    256
#define HIDDEN    128
#define OUT_DIM   17
#define LN_EPS    1e-5f
#define CAP       64          // padded CSR capacity; P(deg>64) ~ 1e-9 per edge

// ---------------- scratch (static device globals; zero-initialized at load) ----------------
__device__ int g_cnt[NUM_EDGES];                     // restored to 0 by fused kernel
__device__ int g_csr[(size_t)NUM_EDGES * CAP];       // 12.8 MB padded CSR

// ---------------- packed f32x2 helpers ----------------
__device__ __forceinline__ void fma_f32x2(unsigned long long& d,
                                          unsigned long long a,
                                          unsigned long long b) {
    asm("fma.rn.f32x2 %0, %1, %2, %0;" : "+l"(d) : "l"(a), "l"(b));
}
__device__ __forceinline__ unsigned long long pack_f32x2(float lo, float hi) {
    unsigned long long r;
    asm("mov.b64 %0, {%1, %2};" : "=l"(r) : "f"(lo), "f"(hi));
    return r;
}
__device__ __forceinline__ float2 unpack_f32x2(unsigned long long v) {
    float2 r;
    asm("mov.b64 {%0, %1}, %2;" : "=f"(r.x), "=f"(r.y) : "l"(v));
    return r;
}

// ---------------- K1: build padded CSR in one pass (int4-vectorized) ----------------
__device__ __forceinline__ void fill_one(int e, int n) {
    if ((unsigned)e < NUM_EDGES) {
        int pos = atomicAdd(&g_cnt[e], 1);
        if (pos < CAP)
            g_csr[(size_t)e * CAP + pos] = ((unsigned)n < NUM_NODES) ? n : 0;
    }
}
__global__ void fill_padded_kernel(const int* __restrict__ he) {
    int t = blockIdx.x * blockDim.x + threadIdx.x;
    if (t < NUM_CONN / 4) {
        int4 e4 = __ldg((const int4*)(he + NUM_CONN) + t);   // edge row
        int4 n4 = __ldg((const int4*)he + t);                // node row
        fill_one(e4.x, n4.x);
        fill_one(e4.y, n4.y);
        fill_one(e4.z, n4.z);
        fill_one(e4.w, n4.w);
    }
}

// ---------------- K2: FUSED gather-mean + GEMM1(FFMA2) + LN + ReLU + GEMM2 ----------------
#define ROWS 25
__global__ void __launch_bounds__(128) fused_mlp_kernel(
    const float* __restrict__ nf,
    const float* __restrict__ W1, const float* __restrict__ b1,
    const float* __restrict__ lng, const float* __restrict__ lnb,
    const float* __restrict__ W2, const float* __restrict__ b2,
    float* __restrict__ out)
{
    __shared__ float Xs[ROWS][IN_DIM];       // 25.6 KB
    __shared__ float Hs[ROWS][HIDDEN];       // 12.8 KB
    __shared__ float W2s[HIDDEN * OUT_DIM];  // 8.7 KB
    __shared__ float b2s[OUT_DIM];

    int tid  = threadIdx.x;
    int wid  = tid >> 5, lane = tid & 31;
    int row0 = blockIdx.x * ROWS;

    for (int idx = tid; idx < HIDDEN * OUT_DIM; idx += 128) W2s[idx] = W2[idx];
    if (tid < OUT_DIM) b2s[tid] = b2[tid];

    // ---- gather + mean straight into Xs (warp-per-edge, 2-way unrolled) ----
    for (int r = wid; r < ROWS; r += 4) {
        int e   = row0 + r;
        int cnt = g_cnt[e];                          // broadcast load
        if (lane == 0) g_cnt[e] = 0;                 // restore for next graph replay
        int cl  = cnt < CAP ? cnt : CAP;
        const int* seg = g_csr + (size_t)e * CAP;
        float4 a0 = make_float4(0.f, 0.f, 0.f, 0.f);
        float4 a1 = make_float4(0.f, 0.f, 0.f, 0.f);
        int i = 0;
        for (; i + 2 <= cl; i += 2) {
            int n0 = seg[i];
            int n1 = seg[i + 1];
            const float4* r0 = (const float4*)(nf + (size_t)n0 * IN_DIM);
            const float4* r1 = (const float4*)(nf + (size_t)n1 * IN_DIM);
            float4 u0 = __ldg(&r0[lane]);
            float4 u1 = __ldg(&r0[32 + lane]);
            float4 v0 = __ldg(&r1[lane]);
            float4 v1 = __ldg(&r1[32 + lane]);
            a0.x += u0.x; a0.y += u0.y; a0.z += u0.z; a0.w += u0.w;
            a1.x += u1.x; a1.y += u1.y; a1.z += u1.z; a1.w += u1.w;
            a0.x += v0.x; a0.y += v0.y; a0.z += v0.z; a0.w += v0.w;
            a1.x += v1.x; a1.y += v1.y; a1.z += v1.z; a1.w += v1.w;
        }
        if (i < cl) {
            int n = seg[i];
            const float4* row = (const float4*)(nf + (size_t)n * IN_DIM);
            float4 v0 = __ldg(&row[lane]);
            float4 v1 = __ldg(&row[32 + lane]);
            a0.x += v0.x; a0.y += v0.y; a0.z += v0.z; a0.w += v0.w;
            a1.x += v1.x; a1.y += v1.y; a1.z += v1.z; a1.w += v1.w;
        }
        float inv = 1.f / (float)(cnt > 0 ? cnt : 1);
        a0.x *= inv; a0.y *= inv; a0.z *= inv; a0.w *= inv;
        a1.x *= inv; a1.y *= inv; a1.z *= inv; a1.w *= inv;
        ((float4*)&Xs[r][0])[lane]      = a0;
        ((float4*)&Xs[r][0])[32 + lane] = a1;
    }
    __syncthreads();

    // ---- GEMM1, packed f32x2, software-pipelined W1 loads ----
    unsigned long long acc2[ROWS];
    #pragma unroll
    for (int r = 0; r < ROWS; r++) acc2[r] = 0ULL;

    float w0 = __ldg(&W1[0 * HIDDEN + tid]);
    float w1 = __ldg(&W1[1 * HIDDEN + tid]);
    float w2 = __ldg(&W1[2 * HIDDEN + tid]);
    float w3 = __ldg(&W1[3 * HIDDEN + tid]);

    #pragma unroll 2
    for (int k = 0; k < IN_DIM - 4; k += 4) {
        float n0 = __ldg(&W1[(k + 4) * HIDDEN + tid]);
        float n1 = __ldg(&W1[(k + 5) * HIDDEN + tid]);
        float n2 = __ldg(&W1[(k + 6) * HIDDEN + tid]);
        float n3 = __ldg(&W1[(k + 7) * HIDDEN + tid]);
        unsigned long long wA = pack_f32x2(w0, w1);
        unsigned long long wB = pack_f32x2(w2, w3);
        #pragma unroll
        for (int r = 0; r < ROWS; r++) {
            ulonglong2 xx = *(const ulonglong2*)&Xs[r][k];  // LDS.128 broadcast
            fma_f32x2(acc2[r], xx.x, wA);
            fma_f32x2(acc2[r], xx.y, wB);
        }
        w0 = n0; w1 = n1; w2 = n2; w3 = n3;
    }
    {   // last quad
        unsigned long long wA = pack_f32x2(w0, w1);
        unsigned long long wB = pack_f32x2(w2, w3);
        #pragma unroll
        for (int r = 0; r < ROWS; r++) {
            ulonglong2 xx = *(const ulonglong2*)&Xs[r][IN_DIM - 4];
            fma_f32x2(acc2[r], xx.x, wA);
            fma_f32x2(acc2[r], xx.y, wB);
        }
    }

    float b1v = b1[tid];
    #pragma unroll
    for (int r = 0; r < ROWS; r++) {
        float2 p = unpack_f32x2(acc2[r]);
        Hs[r][tid] = p.x + p.y + b1v;
    }
    __syncthreads();

    // ---- LayerNorm + ReLU, warp-per-row ----
    for (int r = wid; r < ROWS; r += 4) {
        float s = 0.f, s2 = 0.f;
        #pragma unroll
        for (int j = 0; j < 4; j++) {
            float v = Hs[r][lane + 32 * j];
            s += v; s2 += v * v;
        }
        #pragma unroll
        for (int o = 16; o; o >>= 1) {
            s  += __shfl_xor_sync(0xffffffffu, s, o);
            s2 += __shfl_xor_sync(0xffffffffu, s2, o);
        }
        float mu  = s * (1.f / HIDDEN);
        float var = s2 * (1.f / HIDDEN) - mu * mu;
        float rs  = rsqrtf(var + LN_EPS);
        #pragma unroll
        for (int j = 0; j < 4; j++) {
            int c = lane + 32 * j;
            float v = (Hs[r][c] - mu) * rs * lng[c] + lnb[c];
            Hs[r][c] = fmaxf(v, 0.f);
        }
    }
    __syncthreads();

    // ---- GEMM2 ----
    for (int idx = tid; idx < ROWS * OUT_DIM; idx += 128) {
        int r = idx / OUT_DIM, o = idx % OUT_DIM;
        float s = b2s[o];
        #pragma unroll 8
        for (int j = 0; j < HIDDEN; j++) s = fmaf(Hs[r][j], W2s[j * OUT_DIM + o], s);
        out[(size_t)(row0 + r) * OUT_DIM + o] = s;
    }
}

// ---------------- launch ----------------
extern "C" void kernel_launch(void* const* d_in, const int* in_sizes, int n_in,
                              void* d_out, int out_size)
{
    const float* node_features = (const float*)d_in[0];
    const int*   he            = (const int*)d_in[1];   // int32 (JAX x64 disabled)
    const float* W1            = (const float*)d_in[2];
    const float* b1            = (const float*)d_in[3];
    const float* ln_g          = (const float*)d_in[4];
    const float* ln_b          = (const float*)d_in[5];
    const float* W2            = (const float*)d_in[6];
    const float* b2            = (const float*)d_in[7];
    float*       out           = (float*)d_out;

    fill_padded_kernel<<<(NUM_CONN / 4 + 255) / 256, 256>>>(he);
    fused_mlp_kernel<<<NUM_EDGES / ROWS, 128>>>(node_features,
                                                W1, b1, ln_g, ln_b, W2, b2, out);
}

// round 17
// speedup vs baseline: 1.5272x; 1.5272x over previous
#include <cuda_runtime.h>
#include <cstdint>

#define NUM_NODES 100000
#define NUM_EDGES 50000
#define NUM_CONN  800000
#define IN_DIM    256
#define HIDDEN    128
#define OUT_DIM   17
#define LN_EPS    1e-5f

#define SCAN_BLK  256
#define SCAN_NBLK ((NUM_EDGES + SCAN_BLK - 1) / SCAN_BLK)   // 196
#define NWARPS    (SCAN_BLK / 32)                            // 8

// ---------------- scratch (static device globals; zero-initialized at load) ----------------
__device__ int g_counts[NUM_EDGES];          // zeroed by scan_write after use (self-restoring)
__device__ int g_offsets[NUM_EDGES + 1];
__device__ int g_cursor[NUM_EDGES];
__device__ int g_csr[NUM_CONN];
__device__ int g_partials[SCAN_NBLK];

// ---------------- packed f32x2 helpers ----------------
__device__ __forceinline__ void fma_f32x2(unsigned long long& d,
                                          unsigned long long a,
                                          unsigned long long b) {
    asm("fma.rn.f32x2 %0, %1, %2, %0;" : "+l"(d) : "l"(a), "l"(b));
}
__device__ __forceinline__ unsigned long long pack_f32x2(float lo, float hi) {
    unsigned long long r;
    asm("mov.b64 %0, {%1, %2};" : "=l"(r) : "f"(lo), "f"(hi));
    return r;
}
__device__ __forceinline__ float2 unpack_f32x2(unsigned long long v) {
    float2 r;
    asm("mov.b64 {%0, %1}, %2;" : "=f"(r.x), "=f"(r.y) : "l"(v));
    return r;
}

// ---------------- K1: histogram of edge ids, int4-vectorized ----------------
__global__ void count_kernel(const int* __restrict__ he) {
    int t = blockIdx.x * blockDim.x + threadIdx.x;
    if (t < NUM_CONN / 4) {
        int4 e4 = __ldg((const int4*)(he + NUM_CONN) + t);
        if ((unsigned)e4.x < NUM_EDGES) atomicAdd(&g_counts[e4.x], 1);
        if ((unsigned)e4.y < NUM_EDGES) atomicAdd(&g_counts[e4.y], 1);
        if ((unsigned)e4.z < NUM_EDGES) atomicAdd(&g_counts[e4.z], 1);
        if ((unsigned)e4.w < NUM_EDGES) atomicAdd(&g_counts[e4.w], 1);
    }
}

// ---------------- K2a: per-block reduce of counts ----------------
__global__ void __launch_bounds__(SCAN_BLK) scan_reduce_kernel() {
    __shared__ int ws[NWARPS];
    int i = blockIdx.x * SCAN_BLK + threadIdx.x;
    int v = (i < NUM_EDGES) ? g_counts[i] : 0;
    int lane = threadIdx.x & 31, wid = threadIdx.x >> 5;
    #pragma unroll
    for (int o = 16; o; o >>= 1) v += __shfl_xor_sync(0xffffffffu, v, o);
    if (lane == 0) ws[wid] = v;
    __syncthreads();
    if (threadIdx.x < NWARPS) {
        int s = ws[threadIdx.x];
        #pragma unroll
        for (int o = NWARPS / 2; o; o >>= 1) s += __shfl_xor_sync(0xffu, s, o);
        if (threadIdx.x == 0) g_partials[blockIdx.x] = s;
    }
}

// ---------------- K2b: per-block scan; predecessor-sum computed locally ----------------
__global__ void __launch_bounds__(SCAN_BLK) scan_write_kernel() {
    __shared__ int ws[NWARPS];
    __shared__ int ws2[NWARPS];
    __shared__ int base_sh;
    __shared__ int tot_sh;
    int tid  = threadIdx.x;
    int lane = tid & 31, wid = tid >> 5;

    {
        int lim = blockIdx.x;
        int s = 0, stot = 0;
        for (int j = tid; j < SCAN_NBLK; j += SCAN_BLK) {
            int p = g_partials[j];
            stot += p;
            if (j < lim) s += p;
        }
        #pragma unroll
        for (int o = 16; o; o >>= 1) {
            s    += __shfl_xor_sync(0xffffffffu, s, o);
            stot += __shfl_xor_sync(0xffffffffu, stot, o);
        }
        if (lane == 0) { ws[wid] = s; ws2[wid] = stot; }
        __syncthreads();
        if (tid < NWARPS) {
            int x = ws[tid];
            int y = ws2[tid];
            #pragma unroll
            for (int o = NWARPS / 2; o; o >>= 1) {
                x += __shfl_xor_sync(0xffu, x, o);
                y += __shfl_xor_sync(0xffu, y, o);
            }
            if (tid == 0) { base_sh = x; tot_sh = y; }
        }
        __syncthreads();
        if (blockIdx.x == SCAN_NBLK - 1 && tid == 0)
            g_offsets[NUM_EDGES] = tot_sh;
    }
    int base = base_sh;

    int i = blockIdx.x * SCAN_BLK + tid;
    int v = (i < NUM_EDGES) ? g_counts[i] : 0;
    int x = v;
    #pragma unroll
    for (int off = 1; off < 32; off <<= 1) {
        int t = __shfl_up_sync(0xffffffffu, x, off);
        if (lane >= off) x += t;
    }
    if (lane == 31) ws[wid] = x;
    __syncthreads();
    if (wid == 0 && lane < NWARPS) {
        int t = ws[lane];
        int y = t;
        #pragma unroll
        for (int off = 1; off < NWARPS; off <<= 1) {
            int u = __shfl_up_sync(0xffu, y, off);
            if (lane >= off) y += u;
        }
        ws[lane] = y - t;
    }
    __syncthreads();
    int excl = (x - v) + ws[wid] + base;
    if (i < NUM_EDGES) {
        g_offsets[i] = excl;
        g_cursor[i]  = excl;
        g_counts[i]  = 0;
    }
}

// ---------------- K3: fill CSR ----------------
__global__ void fill_kernel(const int* __restrict__ he) {
    int c = blockIdx.x * blockDim.x + threadIdx.x;
    if (c < NUM_CONN) {
        int e = he[NUM_CONN + c];
        if ((unsigned)e < NUM_EDGES) {
            int pos = atomicAdd(&g_cursor[e], 1);
            int n = he[c];
            g_csr[pos] = ((unsigned)n < NUM_NODES) ? n : 0;
        }
    }
}

// ---------------- K4: FUSED gather-mean + GEMM1(FFMA2) + LN + ReLU + GEMM2 ----------------
// __launch_bounds__(128, 4): cap regs at 128 so 4 blocks/SM fit (was 138 regs -> 3 blocks).
#define ROWS 25
__global__ void __launch_bounds__(128, 4) fused_mlp_kernel(
    const float* __restrict__ nf,
    const float* __restrict__ W1, const float* __restrict__ b1,
    const float* __restrict__ lng, const float* __restrict__ lnb,
    const float* __restrict__ W2, const float* __restrict__ b2,
    float* __restrict__ out)
{
    __shared__ float Xs[ROWS][IN_DIM];       // 25.6 KB
    __shared__ float Hs[ROWS][HIDDEN];       // 12.8 KB
    __shared__ float W2s[HIDDEN * OUT_DIM];  // 8.7 KB
    __shared__ float b2s[OUT_DIM];

    int tid  = threadIdx.x;
    int wid  = tid >> 5, lane = tid & 31;
    int row0 = blockIdx.x * ROWS;

    for (int idx = tid; idx < HIDDEN * OUT_DIM; idx += 128) W2s[idx] = W2[idx];
    if (tid < OUT_DIM) b2s[tid] = b2[tid];

    // ---- gather + mean straight into Xs (warp-per-edge, 2-way unrolled) ----
    for (int r = wid; r < ROWS; r += 4) {
        int e   = row0 + r;
        int beg = g_offsets[e];
        int end = g_offsets[e + 1];
        float4 a0 = make_float4(0.f, 0.f, 0.f, 0.f);
        float4 a1 = make_float4(0.f, 0.f, 0.f, 0.f);
        int i = beg;
        for (; i + 2 <= end; i += 2) {
            int n0 = g_csr[i];
            int n1 = g_csr[i + 1];
            const float4* r0 = (const float4*)(nf + (size_t)n0 * IN_DIM);
            const float4* r1 = (const float4*)(nf + (size_t)n1 * IN_DIM);
            float4 u0 = __ldg(&r0[lane]);
            float4 u1 = __ldg(&r0[32 + lane]);
            float4 v0 = __ldg(&r1[lane]);
            float4 v1 = __ldg(&r1[32 + lane]);
            a0.x += u0.x; a0.y += u0.y; a0.z += u0.z; a0.w += u0.w;
            a1.x += u1.x; a1.y += u1.y; a1.z += u1.z; a1.w += u1.w;
            a0.x += v0.x; a0.y += v0.y; a0.z += v0.z; a0.w += v0.w;
            a1.x += v1.x; a1.y += v1.y; a1.z += v1.z; a1.w += v1.w;
        }
        if (i < end) {
            int n = g_csr[i];
            const float4* row = (const float4*)(nf + (size_t)n * IN_DIM);
            float4 v0 = __ldg(&row[lane]);
            float4 v1 = __ldg(&row[32 + lane]);
            a0.x += v0.x; a0.y += v0.y; a0.z += v0.z; a0.w += v0.w;
            a1.x += v1.x; a1.y += v1.y; a1.z += v1.z; a1.w += v1.w;
        }
        int cnt = end - beg;
        float inv = 1.f / (float)(cnt > 0 ? cnt : 1);
        a0.x *= inv; a0.y *= inv; a0.z *= inv; a0.w *= inv;
        a1.x *= inv; a1.y *= inv; a1.z *= inv; a1.w *= inv;
        ((float4*)&Xs[r][0])[lane]      = a0;
        ((float4*)&Xs[r][0])[32 + lane] = a1;
    }
    __syncthreads();

    // ---- GEMM1, packed f32x2, software-pipelined W1 loads ----
    unsigned long long acc2[ROWS];
    #pragma unroll
    for (int r = 0; r < ROWS; r++) acc2[r] = 0ULL;

    float w0 = __ldg(&W1[0 * HIDDEN + tid]);
    float w1 = __ldg(&W1[1 * HIDDEN + tid]);
    float w2 = __ldg(&W1[2 * HIDDEN + tid]);
    float w3 = __ldg(&W1[3 * HIDDEN + tid]);

    #pragma unroll 2
    for (int k = 0; k < IN_DIM - 4; k += 4) {
        float n0 = __ldg(&W1[(k + 4) * HIDDEN + tid]);
        float n1 = __ldg(&W1[(k + 5) * HIDDEN + tid]);
        float n2 = __ldg(&W1[(k + 6) * HIDDEN + tid]);
        float n3 = __ldg(&W1[(k + 7) * HIDDEN + tid]);
        unsigned long long wA = pack_f32x2(w0, w1);
        unsigned long long wB = pack_f32x2(w2, w3);
        #pragma unroll
        for (int r = 0; r < ROWS; r++) {
            ulonglong2 xx = *(const ulonglong2*)&Xs[r][k];  // LDS.128 broadcast
            fma_f32x2(acc2[r], xx.x, wA);
            fma_f32x2(acc2[r], xx.y, wB);
        }
        w0 = n0; w1 = n1; w2 = n2; w3 = n3;
    }
    {   // last quad
        unsigned long long wA = pack_f32x2(w0, w1);
        unsigned long long wB = pack_f32x2(w2, w3);
        #pragma unroll
        for (int r = 0; r < ROWS; r++) {
            ulonglong2 xx = *(const ulonglong2*)&Xs[r][IN_DIM - 4];
            fma_f32x2(acc2[r], xx.x, wA);
            fma_f32x2(acc2[r], xx.y, wB);
        }
    }

    float b1v = b1[tid];
    #pragma unroll
    for (int r = 0; r < ROWS; r++) {
        float2 p = unpack_f32x2(acc2[r]);
        Hs[r][tid] = p.x + p.y + b1v;
    }
    __syncthreads();

    // ---- LayerNorm + ReLU, warp-per-row ----
    for (int r = wid; r < ROWS; r += 4) {
        float s = 0.f, s2 = 0.f;
        #pragma unroll
        for (int j = 0; j < 4; j++) {
            float v = Hs[r][lane + 32 * j];
            s += v; s2 += v * v;
        }
        #pragma unroll
        for (int o = 16; o; o >>= 1) {
            s  += __shfl_xor_sync(0xffffffffu, s, o);
            s2 += __shfl_xor_sync(0xffffffffu, s2, o);
        }
        float mu  = s * (1.f / HIDDEN);
        float var = s2 * (1.f / HIDDEN) - mu * mu;
        float rs  = rsqrtf(var + LN_EPS);
        #pragma unroll
        for (int j = 0; j < 4; j++) {
            int c = lane + 32 * j;
            float v = (Hs[r][c] - mu) * rs * lng[c] + lnb[c];
            Hs[r][c] = fmaxf(v, 0.f);
        }
    }
    __syncthreads();

    // ---- GEMM2 ----
    for (int idx = tid; idx < ROWS * OUT_DIM; idx += 128) {
        int r = idx / OUT_DIM, o = idx % OUT_DIM;
        float s = b2s[o];
        #pragma unroll 8
        for (int j = 0; j < HIDDEN; j++) s = fmaf(Hs[r][j], W2s[j * OUT_DIM + o], s);
        out[(size_t)(row0 + r) * OUT_DIM + o] = s;
    }
}

// ---------------- launch ----------------
extern "C" void kernel_launch(void* const* d_in, const int* in_sizes, int n_in,
                              void* d_out, int out_size)
{
    const float* node_features = (const float*)d_in[0];
    const int*   he            = (const int*)d_in[1];   // int32 (JAX x64 disabled)
    const float* W1            = (const float*)d_in[2];
    const float* b1            = (const float*)d_in[3];
    const float* ln_g          = (const float*)d_in[4];
    const float* ln_b          = (const float*)d_in[5];
    const float* W2            = (const float*)d_in[6];
    const float* b2            = (const float*)d_in[7];
    float*       out           = (float*)d_out;

    count_kernel<<<(NUM_CONN / 4 + 255) / 256, 256>>>(he);
    scan_reduce_kernel<<<SCAN_NBLK, SCAN_BLK>>>();
    scan_write_kernel<<<SCAN_NBLK, SCAN_BLK>>>();
    fill_kernel<<<(NUM_CONN + 255) / 256, 256>>>(he);
    fused_mlp_kernel<<<NUM_EDGES / ROWS, 128>>>(node_features,
                                                W1, b1, ln_g, ln_b, W2, b2, out);
}